// round 16
// baseline (speedup 1.0000x reference)
#include <cuda_runtime.h>
#include <math.h>
#include <stdint.h>

#define TT 512
#define BB 64
#define DD 512
#define HH 512
#define GG 2048
#define KTOT 1024
#define P3_NCTA 128
#define NTHR 512

typedef unsigned long long u64;

// ---------------- device scratch ----------------
__device__ float g_W[(size_t)GG * KTOT];        // 8 MB normalized weights
__device__ float g_Xt[(size_t)TT * DD * BB];    // 64 MB X transposed [t][d][b]
__device__ float g_h[2][(size_t)HH * BB];       // h double buffer, [col][b]
__device__ unsigned g_flagv[P3_NCTA][32];       // per-CTA step flags (128B lines)

// ---------------- f32x2 helpers ----------------
__device__ __forceinline__ u64 pack2(float x, float y) {
    u64 r; asm("mov.b64 %0, {%1, %2};" : "=l"(r) : "f"(x), "f"(y)); return r;
}
__device__ __forceinline__ void fma2(u64& d, u64 a, u64 b) {
    asm("fma.rn.f32x2 %0, %1, %2, %0;" : "+l"(d) : "l"(a), "l"(b));
}
__device__ __forceinline__ float2 unpack2(u64 v) {
    float2 f; asm("mov.b64 {%0, %1}, %2;" : "=f"(f.x), "=f"(f.y) : "l"(v)); return f;
}

// ---------------- cp.async (L2-only) ----------------
__device__ __forceinline__ void cp_async16(void* smem_dst, const void* gsrc) {
    unsigned s = (unsigned)__cvta_generic_to_shared(smem_dst);
    asm volatile("cp.async.cg.shared.global [%0], [%1], 16;" :: "r"(s), "l"(gsrc));
}
#define CP_COMMIT() asm volatile("cp.async.commit_group;" ::: "memory")
#define CP_WAIT(n)  asm volatile("cp.async.wait_group %0;" :: "n"(n) : "memory")

__device__ __forceinline__ unsigned ld_acq(const unsigned* p) {
    unsigned v;
    asm volatile("ld.acquire.gpu.u32 %0, [%1];" : "=r"(v) : "l"(p) : "memory");
    return v;
}

__device__ __forceinline__ float sigf(float x) { return 1.0f / (1.0f + expf(-x)); }

// ============================================================================
// Phase 0: per-replay init — zero flags + h buffer 0
// ============================================================================
__global__ __launch_bounds__(256) void qlstm_init() {
    int tid = blockIdx.x * 256 + threadIdx.x;    // grid 128 x 256 = 32768
    ((float*)g_h)[tid] = 0.0f;                   // zeroes g_h[0] exactly
    if (tid < P3_NCTA * 32) ((unsigned*)g_flagv)[tid] = 0u;
}

// ============================================================================
// Phase 1: weight norm
// ============================================================================
__global__ __launch_bounds__(256) void qlstm_wnorm(const float* __restrict__ v,
                                                   const float* __restrict__ g) {
    int r = blockIdx.x;
    const float* vr = v + (size_t)r * KTOT;
    float s = 0.0f;
    for (int k = threadIdx.x; k < KTOT; k += 256) { float x = vr[k]; s += x * x; }
    __shared__ float red[256];
    red[threadIdx.x] = s;
    __syncthreads();
    for (int off = 128; off > 0; off >>= 1) {
        if (threadIdx.x < off) red[threadIdx.x] += red[threadIdx.x + off];
        __syncthreads();
    }
    float scale = g[r] * rsqrtf(red[0]);
    for (int k = threadIdx.x; k < KTOT; k += 256)
        g_W[(size_t)r * KTOT + k] = vr[k] * scale;
}

// ============================================================================
// Phase 1.5: transpose X[t][b][d] -> Xt[t][d][b]
// ============================================================================
__global__ __launch_bounds__(256) void qlstm_xpose(const float* __restrict__ X) {
    __shared__ float tile[64 * 65];
    const int t  = blockIdx.x;
    const int d0 = blockIdx.y * 64;
    const int dx = threadIdx.x & 63, bq = threadIdx.x >> 6;
    #pragma unroll
    for (int i = 0; i < 16; i++) {
        int b = bq + i * 4;
        tile[dx * 65 + b] = X[((size_t)t * BB + b) * DD + d0 + dx];
    }
    __syncthreads();
    const int bx = threadIdx.x & 63, dq = threadIdx.x >> 6;
    #pragma unroll
    for (int i = 0; i < 16; i++) {
        int d = dq + i * 4;
        g_Xt[((size_t)t * DD + d0 + d) * BB + bx] = tile[d * 65 + bx];
    }
}

// ============================================================================
// Phase 3: FUSED persistent recurrence (R15 core) at 512 threads / 16 warps.
// Warp = (k-slice of 64) x (batch-half of 32); thread tile 4 rows x 4 batches.
// Each warp stages only its own batch columns of the shared ss slice.
// ============================================================================
#define WS_PAD 516
#define OFF_WX  (16 * WS_PAD * 4)            // 33024
#define OFF_SS  (OFF_WX + 16 * WS_PAD * 4)   // 66048
#define OFF_ZSP (OFF_SS + 131072)            // 197120
#define SM_BYTES (OFF_ZSP + 32768)           // 229888

__global__ __launch_bounds__(NTHR) void qlstm_recur(const float* __restrict__ bias,
                                                    float* __restrict__ out, int out_size) {
    extern __shared__ unsigned char smraw[];
    float* Whs = (float*)smraw;                     // [16][516] recurrent W
    float* Wxs = (float*)(smraw + OFF_WX);          // [16][516] input W
    float* ss  = (float*)(smraw + OFF_SS);          // [512 k][64 b] shared x/h buffer
    float* zsp = (float*)(smraw + OFF_ZSP);         // [8 ks][16 r][64 b]

    const int tid = threadIdx.x;
    const int bc  = blockIdx.x;
    const int c0  = bc * 4;

    // load both weight slices
    #pragma unroll
    for (int u = 0; u < 16; u++) {
        int idx = tid + u * NTHR;
        int lr = idx >> 9, k = idx & 511;
        int gr = (lr >> 2) * 512 + c0 + (lr & 3);
        Whs[lr * WS_PAD + k] = g_W[(size_t)gr * KTOT + 512 + k];
        Wxs[lr * WS_PAD + k] = g_W[(size_t)gr * KTOT + k];
    }

    const int ep_j = (tid >> 6) & 3, ep_b = tid & 63;
    float bz[4];
    #pragma unroll
    for (int gi = 0; gi < 4; gi++) bz[gi] = bias[gi * 512 + c0 + ep_j];
    float creg = 0.0f, hlast = 0.0f;

    const int wid   = tid >> 5;
    const int ks    = wid >> 1;              // 0..7 warp k-slice (64 of 512)
    const int bh    = wid & 1;               // batch half: 0 -> b 0..31, 1 -> b 32..63
    const int lane  = tid & 31;
    const int rgr   = lane >> 3;             // 0..3: rows rgr, rgr+4, rgr+8, rgr+12
    const int bq8   = lane & 7;              // batch quad within half
    const int b0    = bh * 32 + bq8 * 4;
    const int kbase = ks * 64;
    const unsigned* myflag = &g_flagv[ks * 16 + (lane & 15)][0];
    const float* whb = Whs + rgr * WS_PAD + kbase;
    const float* wxb = Wxs + rgr * WS_PAD + kbase;
    float* ssw = ss + kbase * 64;            // this k-slice's 16KB region
    __syncthreads();

    // prologue: stage x(0) (own batch-half columns: 16B chunk per 8 k-chunks)
    {
        const float* src = g_Xt + (size_t)kbase * BB;
        #pragma unroll
        for (int u = 0; u < 16; u++) {
            int idx = lane + u * 32;          // 0..511: k = idx>>3, chunk = idx&7
            int k = idx >> 3, c8 = idx & 7;
            cp_async16(ssw + k * 64 + bh * 32 + c8 * 4,
                       src + k * 64 + bh * 32 + c8 * 4);
        }
        CP_COMMIT();
    }

    for (int s = 0; s < TT; s++) {
        // x(s) staged by previous step (or prologue)
        CP_WAIT(0);
        __syncwarp();

        u64 acc[4][2];
        #pragma unroll
        for (int r = 0; r < 4; r++) { acc[r][0] = 0ULL; acc[r][1] = 0ULL; }

        const float* sbase = ssw + b0;

        // ---- x-part: from smem; fills the flag-wait window ----
        #pragma unroll 4
        for (int kb = 0; kb < 16; kb++) {
            ulonglong2 xq[4];
            #pragma unroll
            for (int j = 0; j < 4; j++)
                xq[j] = *(const ulonglong2*)(sbase + (kb * 4 + j) * 64);
            #pragma unroll
            for (int rr = 0; rr < 4; rr++) {
                float4 wv = *(const float4*)(wxb + rr * 4 * WS_PAD + kb * 4);
                u64 w0 = pack2(wv.x, wv.x), w1 = pack2(wv.y, wv.y);
                u64 w2 = pack2(wv.z, wv.z), w3 = pack2(wv.w, wv.w);
                fma2(acc[rr][0], w0, xq[0].x); fma2(acc[rr][1], w0, xq[0].y);
                fma2(acc[rr][0], w1, xq[1].x); fma2(acc[rr][1], w1, xq[1].y);
                fma2(acc[rr][0], w2, xq[2].x); fma2(acc[rr][1], w2, xq[2].y);
                fma2(acc[rr][0], w3, xq[3].x); fma2(acc[rr][1], w3, xq[3].y);
            }
        }

        // ---- per-warp flag wait: the 16 producers of my h k-slice ----
        if (s > 0) {
            for (;;) {
                unsigned v = ld_acq(myflag);
                if (__all_sync(0xFFFFFFFFu, v >= (unsigned)s)) break;
                __nanosleep(20);
            }
        }

        // ---- stage h(s) into own columns (overwrites consumed x(s)) ----
        {
            const float* src = g_h[s & 1] + kbase * 64;
            #pragma unroll
            for (int u = 0; u < 16; u++) {
                int idx = lane + u * 32;
                int k = idx >> 3, c8 = idx & 7;
                cp_async16(ssw + k * 64 + bh * 32 + c8 * 4,
                           src + k * 64 + bh * 32 + c8 * 4);
            }
            CP_COMMIT();
            CP_WAIT(0);
            __syncwarp();
        }

        // ---- h-part: accumulate into same registers ----
        #pragma unroll 4
        for (int kb = 0; kb < 16; kb++) {
            ulonglong2 hq[4];
            #pragma unroll
            for (int j = 0; j < 4; j++)
                hq[j] = *(const ulonglong2*)(sbase + (kb * 4 + j) * 64);
            #pragma unroll
            for (int rr = 0; rr < 4; rr++) {
                float4 wv = *(const float4*)(whb + rr * 4 * WS_PAD + kb * 4);
                u64 w0 = pack2(wv.x, wv.x), w1 = pack2(wv.y, wv.y);
                u64 w2 = pack2(wv.z, wv.z), w3 = pack2(wv.w, wv.w);
                fma2(acc[rr][0], w0, hq[0].x); fma2(acc[rr][1], w0, hq[0].y);
                fma2(acc[rr][0], w1, hq[1].x); fma2(acc[rr][1], w1, hq[1].y);
                fma2(acc[rr][0], w2, hq[2].x); fma2(acc[rr][1], w2, hq[2].y);
                fma2(acc[rr][0], w3, hq[3].x); fma2(acc[rr][1], w3, hq[3].y);
            }
        }

        // ---- issue x(s+1) staging (own columns; pair warp reads are disjoint)
        {
            int sn = (s + 1 < TT) ? s + 1 : s;
            const float* src = g_Xt + ((size_t)sn * DD + kbase) * BB;
            #pragma unroll
            for (int u = 0; u < 16; u++) {
                int idx = lane + u * 32;
                int k = idx >> 3, c8 = idx & 7;
                cp_async16(ssw + k * 64 + bh * 32 + c8 * 4,
                           src + k * 64 + bh * 32 + c8 * 4);
            }
            CP_COMMIT();
        }

        // ---- k-split partials ----
        #pragma unroll
        for (int rr = 0; rr < 4; rr++) {
            int lr = rgr + rr * 4;
            float2 a = unpack2(acc[rr][0]);
            float2 c2 = unpack2(acc[rr][1]);
            *(float4*)&zsp[(ks * 16 + lr) * 64 + b0] = make_float4(a.x, a.y, c2.x, c2.y);
        }
        __syncthreads();

        // ---- gate epilogue (first 256 threads) ----
        if (tid < 256) {
            float z[4];
            #pragma unroll
            for (int gi = 0; gi < 4; gi++) {
                int row = gi * 4 + ep_j;
                float ssum = bz[gi];
                #pragma unroll
                for (int q = 0; q < 8; q++)
                    ssum += zsp[(q * 16 + row) * 64 + ep_b];
                z[gi] = ssum;
            }
            float fg = sigf(z[0]), ig = sigf(z[1]), ug = tanhf(z[2]), og = sigf(z[3]);
            creg = fg * creg + ig * ug;
            float hv = og * tanhf(creg);
            hlast = hv;
            g_h[(s + 1) & 1][(size_t)(c0 + ep_j) * BB + ep_b] = hv;
        }
        __syncthreads();
        if (tid == 0) {
            __threadfence();
            *(volatile unsigned*)&g_flagv[bc][0] = (unsigned)(s + 1);
        }
        if (tid < 256)
            out[((size_t)s * BB + ep_b) * HH + c0 + ep_j] = hlast;
    }

    size_t TBH = (size_t)TT * BB * HH;
    if (tid < 256 && (size_t)out_size >= TBH + 2 * (size_t)BB * HH) {
        out[TBH + (size_t)ep_b * HH + c0 + ep_j] = hlast;
        out[TBH + (size_t)BB * HH + (size_t)ep_b * HH + c0 + ep_j] = creg;
    }
}

extern "C" void kernel_launch(void* const* d_in, const int* in_sizes, int n_in,
                              void* d_out, int out_size) {
    const float* X  = (const float*)d_in[0];
    const float* v  = (const float*)d_in[1];
    const float* g  = (const float*)d_in[2];
    const float* b  = (const float*)d_in[3];
    float* out = (float*)d_out;

    cudaFuncSetAttribute(qlstm_recur, cudaFuncAttributeMaxDynamicSharedMemorySize, SM_BYTES);

    qlstm_wnorm<<<GG, 256>>>(v, g);
    qlstm_xpose<<<dim3(TT, DD / 64), 256>>>(X);
    qlstm_init<<<P3_NCTA, 256>>>();
    qlstm_recur<<<P3_NCTA, NTHR, SM_BYTES>>>(b, out, out_size);
}

// round 17
// speedup vs baseline: 1.0755x; 1.0755x over previous
#include <cuda_runtime.h>
#include <math.h>
#include <stdint.h>

#define TT 512
#define BB 64
#define DD 512
#define HH 512
#define GG 2048
#define KTOT 1024
#define P3_NCTA 128
#define NTHR 512

typedef unsigned long long u64;

// ---------------- device scratch ----------------
__device__ float g_W[(size_t)GG * KTOT];        // 8 MB normalized weights
__device__ float g_Xt[(size_t)TT * DD * BB];    // 64 MB X transposed [t][d][b]
__device__ float g_h[2][(size_t)HH * BB];       // h double buffer, [col][b]
__device__ unsigned g_flagv[P3_NCTA][32];       // per-CTA step flags (128B lines)

// ---------------- f32x2 helpers ----------------
__device__ __forceinline__ u64 pack2(float x, float y) {
    u64 r; asm("mov.b64 %0, {%1, %2};" : "=l"(r) : "f"(x), "f"(y)); return r;
}
__device__ __forceinline__ void fma2(u64& d, u64 a, u64 b) {
    asm("fma.rn.f32x2 %0, %1, %2, %0;" : "+l"(d) : "l"(a), "l"(b));
}
__device__ __forceinline__ float2 unpack2(u64 v) {
    float2 f; asm("mov.b64 {%0, %1}, %2;" : "=f"(f.x), "=f"(f.y) : "l"(v)); return f;
}

// ---------------- cp.async (L2-only) ----------------
__device__ __forceinline__ void cp_async16(void* smem_dst, const void* gsrc) {
    unsigned s = (unsigned)__cvta_generic_to_shared(smem_dst);
    asm volatile("cp.async.cg.shared.global [%0], [%1], 16;" :: "r"(s), "l"(gsrc));
}
#define CP_COMMIT() asm volatile("cp.async.commit_group;" ::: "memory")
#define CP_WAIT(n)  asm volatile("cp.async.wait_group %0;" :: "n"(n) : "memory")

__device__ __forceinline__ unsigned ld_acq(const unsigned* p) {
    unsigned v;
    asm volatile("ld.acquire.gpu.u32 %0, [%1];" : "=r"(v) : "l"(p) : "memory");
    return v;
}

__device__ __forceinline__ float sigf(float x) { return 1.0f / (1.0f + expf(-x)); }

// ============================================================================
// Phase 0: per-replay init — zero flags + h buffer 0
// ============================================================================
__global__ __launch_bounds__(256) void qlstm_init() {
    int tid = blockIdx.x * 256 + threadIdx.x;    // grid 128 x 256 = 32768
    ((float*)g_h)[tid] = 0.0f;                   // zeroes g_h[0] exactly
    if (tid < P3_NCTA * 32) ((unsigned*)g_flagv)[tid] = 0u;
}

// ============================================================================
// Phase 1: weight norm
// ============================================================================
__global__ __launch_bounds__(256) void qlstm_wnorm(const float* __restrict__ v,
                                                   const float* __restrict__ g) {
    int r = blockIdx.x;
    const float* vr = v + (size_t)r * KTOT;
    float s = 0.0f;
    for (int k = threadIdx.x; k < KTOT; k += 256) { float x = vr[k]; s += x * x; }
    __shared__ float red[256];
    red[threadIdx.x] = s;
    __syncthreads();
    for (int off = 128; off > 0; off >>= 1) {
        if (threadIdx.x < off) red[threadIdx.x] += red[threadIdx.x + off];
        __syncthreads();
    }
    float scale = g[r] * rsqrtf(red[0]);
    for (int k = threadIdx.x; k < KTOT; k += 256)
        g_W[(size_t)r * KTOT + k] = vr[k] * scale;
}

// ============================================================================
// Phase 1.5: transpose X[t][b][d] -> Xt[t][d][b]
// ============================================================================
__global__ __launch_bounds__(256) void qlstm_xpose(const float* __restrict__ X) {
    __shared__ float tile[64 * 65];
    const int t  = blockIdx.x;
    const int d0 = blockIdx.y * 64;
    const int dx = threadIdx.x & 63, bq = threadIdx.x >> 6;
    #pragma unroll
    for (int i = 0; i < 16; i++) {
        int b = bq + i * 4;
        tile[dx * 65 + b] = X[((size_t)t * BB + b) * DD + d0 + dx];
    }
    __syncthreads();
    const int bx = threadIdx.x & 63, dq = threadIdx.x >> 6;
    #pragma unroll
    for (int i = 0; i < 16; i++) {
        int d = dq + i * 4;
        g_Xt[((size_t)t * DD + d0 + d) * BB + bx] = tile[d * 65 + bx];
    }
}

// ============================================================================
// Phase 3: FUSED persistent recurrence — 16 warps, warp = 32-k slice,
// thread tile 8 rows x 4 batches (LDS 3 B/fma2, same as the 3781us R15 core).
// zsp reduced in two waves (ks<8 write, ks>=8 add) to stay at 32KB.
// ============================================================================
#define WS_PAD 516
#define OFF_WX  (16 * WS_PAD * 4)            // 33024
#define OFF_SS  (OFF_WX + 16 * WS_PAD * 4)   // 66048
#define OFF_ZSP (OFF_SS + 131072)            // 197120
#define SM_BYTES (OFF_ZSP + 32768)           // 229888

__global__ __launch_bounds__(NTHR) void qlstm_recur(const float* __restrict__ bias,
                                                    float* __restrict__ out, int out_size) {
    extern __shared__ unsigned char smraw[];
    float* Whs = (float*)smraw;                     // [16][516] recurrent W
    float* Wxs = (float*)(smraw + OFF_WX);          // [16][516] input W
    float* ss  = (float*)(smraw + OFF_SS);          // [512 k][64 b] shared x/h buffer
    float* zsp = (float*)(smraw + OFF_ZSP);         // [8][16 r][64 b]

    const int tid = threadIdx.x;
    const int bc  = blockIdx.x;
    const int c0  = bc * 4;

    // load both weight slices
    #pragma unroll
    for (int u = 0; u < 16; u++) {
        int idx = tid + u * NTHR;
        int lr = idx >> 9, k = idx & 511;
        int gr = (lr >> 2) * 512 + c0 + (lr & 3);
        Whs[lr * WS_PAD + k] = g_W[(size_t)gr * KTOT + 512 + k];
        Wxs[lr * WS_PAD + k] = g_W[(size_t)gr * KTOT + k];
    }

    const int ep_j = (tid >> 6) & 3, ep_b = tid & 63;
    float bz[4];
    #pragma unroll
    for (int gi = 0; gi < 4; gi++) bz[gi] = bias[gi * 512 + c0 + ep_j];
    float creg = 0.0f, hlast = 0.0f;

    const int ks    = tid >> 5;              // 0..15: warp = 32-k slice
    const int lane  = tid & 31;
    const int rgi   = (lane >> 4) & 1;       // row interleave bit
    const int b0    = (lane & 15) * 4;
    const int kbase = ks * 32;
    const int zq    = ks & 7;                // zsp slot (pairs ks, ks+8 share)
    const unsigned* myflag = &g_flagv[ks * 8 + (lane & 7)][0];
    const float* whb = Whs + rgi * WS_PAD + kbase;
    const float* wxb = Wxs + rgi * WS_PAD + kbase;
    float* ssw = ss + kbase * 64;            // this warp's exclusive 8KB slice
    __syncthreads();

    // prologue: stage x(0) into own slice (512 x 16B chunks)
    {
        const float* src = g_Xt + (size_t)kbase * BB;
        #pragma unroll
        for (int u = 0; u < 16; u++) {
            int idx = lane + u * 32;
            cp_async16(ssw + idx * 4, src + idx * 4);
        }
        CP_COMMIT();
    }

    for (int s = 0; s < TT; s++) {
        // x(s) staged by previous step (or prologue)
        CP_WAIT(0);
        __syncwarp();

        u64 acc[8][2];
        #pragma unroll
        for (int r = 0; r < 8; r++) { acc[r][0] = 0ULL; acc[r][1] = 0ULL; }

        const float* sbase = ssw + b0;

        // ---- x-part: from smem; fills the flag-wait window ----
        #pragma unroll 4
        for (int kb = 0; kb < 8; kb++) {
            ulonglong2 xq[4];
            #pragma unroll
            for (int j = 0; j < 4; j++)
                xq[j] = *(const ulonglong2*)(sbase + (kb * 4 + j) * 64);
            #pragma unroll
            for (int rr = 0; rr < 8; rr++) {
                float4 wv = *(const float4*)(wxb + rr * 2 * WS_PAD + kb * 4);
                u64 w0 = pack2(wv.x, wv.x), w1 = pack2(wv.y, wv.y);
                u64 w2 = pack2(wv.z, wv.z), w3 = pack2(wv.w, wv.w);
                fma2(acc[rr][0], w0, xq[0].x); fma2(acc[rr][1], w0, xq[0].y);
                fma2(acc[rr][0], w1, xq[1].x); fma2(acc[rr][1], w1, xq[1].y);
                fma2(acc[rr][0], w2, xq[2].x); fma2(acc[rr][1], w2, xq[2].y);
                fma2(acc[rr][0], w3, xq[3].x); fma2(acc[rr][1], w3, xq[3].y);
            }
        }

        // ---- per-warp flag wait: the 8 producers of my 32-k h slice ----
        if (s > 0) {
            for (;;) {
                unsigned v = ld_acq(myflag);
                if (__all_sync(0xFFFFFFFFu, v >= (unsigned)s)) break;
                __nanosleep(20);
            }
        }

        // ---- stage h(s) into own slice (overwrites consumed x(s)) ----
        {
            const float* src = g_h[s & 1] + kbase * 64;
            #pragma unroll
            for (int u = 0; u < 16; u++) {
                int idx = lane + u * 32;
                cp_async16(ssw + idx * 4, src + idx * 4);
            }
            CP_COMMIT();
            CP_WAIT(0);
            __syncwarp();
        }

        // ---- h-part: accumulate into same registers ----
        #pragma unroll 4
        for (int kb = 0; kb < 8; kb++) {
            ulonglong2 hq[4];
            #pragma unroll
            for (int j = 0; j < 4; j++)
                hq[j] = *(const ulonglong2*)(sbase + (kb * 4 + j) * 64);
            #pragma unroll
            for (int rr = 0; rr < 8; rr++) {
                float4 wv = *(const float4*)(whb + rr * 2 * WS_PAD + kb * 4);
                u64 w0 = pack2(wv.x, wv.x), w1 = pack2(wv.y, wv.y);
                u64 w2 = pack2(wv.z, wv.z), w3 = pack2(wv.w, wv.w);
                fma2(acc[rr][0], w0, hq[0].x); fma2(acc[rr][1], w0, hq[0].y);
                fma2(acc[rr][0], w1, hq[1].x); fma2(acc[rr][1], w1, hq[1].y);
                fma2(acc[rr][0], w2, hq[2].x); fma2(acc[rr][1], w2, hq[2].y);
                fma2(acc[rr][0], w3, hq[3].x); fma2(acc[rr][1], w3, hq[3].y);
            }
        }

        // ---- issue x(s+1) staging: lands during epilogue + next x window ----
        {
            int sn = (s + 1 < TT) ? s + 1 : s;
            const float* src = g_Xt + ((size_t)sn * DD + kbase) * BB;
            #pragma unroll
            for (int u = 0; u < 16; u++) {
                int idx = lane + u * 32;
                cp_async16(ssw + idx * 4, src + idx * 4);
            }
            CP_COMMIT();
        }

        // ---- zsp two-wave reduction: ks<8 write, then ks>=8 add ----
        if (ks < 8) {
            #pragma unroll
            for (int rr = 0; rr < 8; rr++) {
                int lr = rr * 2 + rgi;
                float2 a = unpack2(acc[rr][0]);
                float2 c2 = unpack2(acc[rr][1]);
                *(float4*)&zsp[(zq * 16 + lr) * 64 + b0] = make_float4(a.x, a.y, c2.x, c2.y);
            }
        }
        __syncthreads();
        if (ks >= 8) {
            #pragma unroll
            for (int rr = 0; rr < 8; rr++) {
                int lr = rr * 2 + rgi;
                float4* p = (float4*)&zsp[(zq * 16 + lr) * 64 + b0];
                float4 cur = *p;
                float2 a = unpack2(acc[rr][0]);
                float2 c2 = unpack2(acc[rr][1]);
                *p = make_float4(cur.x + a.x, cur.y + a.y, cur.z + c2.x, cur.w + c2.y);
            }
        }
        __syncthreads();

        // ---- gate epilogue (first 256 threads) ----
        if (tid < 256) {
            float z[4];
            #pragma unroll
            for (int gi = 0; gi < 4; gi++) {
                int row = gi * 4 + ep_j;
                float ssum = bz[gi];
                #pragma unroll
                for (int q = 0; q < 8; q++)
                    ssum += zsp[(q * 16 + row) * 64 + ep_b];
                z[gi] = ssum;
            }
            float fg = sigf(z[0]), ig = sigf(z[1]), ug = tanhf(z[2]), og = sigf(z[3]);
            creg = fg * creg + ig * ug;
            float hv = og * tanhf(creg);
            hlast = hv;
            g_h[(s + 1) & 1][(size_t)(c0 + ep_j) * BB + ep_b] = hv;
        }
        __syncthreads();
        if (tid == 0) {
            __threadfence();
            *(volatile unsigned*)&g_flagv[bc][0] = (unsigned)(s + 1);
        }
        if (tid < 256)
            out[((size_t)s * BB + ep_b) * HH + c0 + ep_j] = hlast;
    }

    size_t TBH = (size_t)TT * BB * HH;
    if (tid < 256 && (size_t)out_size >= TBH + 2 * (size_t)BB * HH) {
        out[TBH + (size_t)ep_b * HH + c0 + ep_j] = hlast;
        out[TBH + (size_t)BB * HH + (size_t)ep_b * HH + c0 + ep_j] = creg;
    }
}

extern "C" void kernel_launch(void* const* d_in, const int* in_sizes, int n_in,
                              void* d_out, int out_size) {
    const float* X  = (const float*)d_in[0];
    const float* v  = (const float*)d_in[1];
    const float* g  = (const float*)d_in[2];
    const float* b  = (const float*)d_in[3];
    float* out = (float*)d_out;

    cudaFuncSetAttribute(qlstm_recur, cudaFuncAttributeMaxDynamicSharedMemorySize, SM_BYTES);

    qlstm_wnorm<<<GG, 256>>>(v, g);
    qlstm_xpose<<<dim3(TT, DD / 64), 256>>>(X);
    qlstm_init<<<P3_NCTA, 256>>>();
    qlstm_recur<<<P3_NCTA, NTHR, SM_BYTES>>>(b, out, out_size);
}